// round 6
// baseline (speedup 1.0000x reference)
#include <cuda_runtime.h>

#define N_NODES 50000
#define N_EDGES 500000
#define NUMK 4
#define FDIM 64
#define DDIM 32
#define NBE 64
#define NBND 63
#define GP 68
#define FULL 0xffffffffu
#define SCAN_B 1024
#define NSCAN ((N_NODES + SCAN_B - 1) / SCAN_B)

// Scratch (device globals)
__device__ __align__(128) float g_y[(size_t)N_NODES * 128];
__device__ float g_s[N_NODES];
__device__ int g_cin[N_NODES];
__device__ int g_cout[N_NODES];
__device__ int g_start[N_NODES];
__device__ int g_cur[N_NODES];
__device__ int g_total;
__device__ __align__(128) float g_T[NBE * FDIM];
__device__ __align__(16) int4 g_eh1[N_EDGES];   // {src, dst, pk0, pk1}
__device__ __align__(16) int4 g_eh2[N_EDGES];   // {pk2, pk3, pk4, 0}

// RED without memory clobber: g_y/g_s are never read by this kernel.
__device__ __forceinline__ void red_add4(float* p, float x, float y, float z, float w) {
    asm volatile("red.global.add.v4.f32 [%0], {%1,%2,%3,%4};"
                 :: "l"(p), "f"(x), "f"(y), "f"(z), "f"(w));
}
__device__ __forceinline__ void red_add1(float* p, float x) {
    asm volatile("red.global.add.f32 [%0], %1;" :: "l"(p), "f"(x));
}

// Fused prep: zero y/s/counters/total, build T table.
__global__ __launch_bounds__(256) void k_prep(
    const float* __restrict__ emb, const float* __restrict__ gw)
{
    int i = blockIdx.x * blockDim.x + threadIdx.x;
    int stride = gridDim.x * blockDim.x;
    float4 z = make_float4(0.f, 0.f, 0.f, 0.f);
    float4* y4 = reinterpret_cast<float4*>(g_y);
    for (int j = i; j < N_NODES * 32; j += stride) y4[j] = z;
    for (int j = i; j < N_NODES; j += stride) {
        g_cin[j] = 0; g_cout[j] = 0; g_s[j] = 0.f;
    }
    if (i == 0) g_total = 0;
    for (int j = i; j < NBE * FDIM; j += stride) {
        int b = j >> 6, f = j & 63;
        float acc = 0.f;
#pragma unroll
        for (int d = 0; d < DDIM; d++) acc += emb[b * DDIM + d] * gw[f * DDIM + d];
        g_T[j] = acc;
    }
}

__global__ void k_hist(const int* __restrict__ src, const int* __restrict__ dst) {
    int e = blockIdx.x * blockDim.x + threadIdx.x;
    if (e < N_EDGES) {
        atomicAdd(&g_cin[dst[e]], 1);
        atomicAdd(&g_cout[src[e]], 1);
    }
}

// One-kernel scan: block-local exclusive scan + atomic block base.
__global__ __launch_bounds__(SCAN_B) void k_scan() {
    __shared__ int wsum[32];
    __shared__ int s_base;
    int t = threadIdx.x, lane = t & 31, wid = t >> 5;
    int i = blockIdx.x * SCAN_B + t;
    int v = (i < N_NODES) ? g_cin[i] : 0;
    int x = v;
#pragma unroll
    for (int off = 1; off < 32; off <<= 1) {
        int u = __shfl_up_sync(FULL, x, off);
        if (lane >= off) x += u;
    }
    if (lane == 31) wsum[wid] = x;
    __syncthreads();
    if (wid == 0) {
        int y = wsum[lane];
#pragma unroll
        for (int off = 1; off < 32; off <<= 1) {
            int zz = __shfl_up_sync(FULL, y, off);
            if (lane >= off) y += zz;
        }
        wsum[lane] = y;
    }
    __syncthreads();
    int excl = x - v + (wid > 0 ? wsum[wid - 1] : 0);
    if (t == SCAN_B - 1) s_base = atomicAdd(&g_total, excl + v);
    __syncthreads();
    if (i < N_NODES) {
        int s0 = s_base + excl;
        g_start[i] = s0;
        g_cur[i] = s0;
    }
}

// Fused scatter + distance/bucket: one thread per edge. Writes packed
// headers into the edge's CSR slot.
__global__ __launch_bounds__(256) void k_scat(
    const float* __restrict__ loc, const float* __restrict__ bnd,
    const int* __restrict__ src, const int* __restrict__ dst,
    const int* __restrict__ inter)
{
    __shared__ float sb[64];
    int t = threadIdx.x;
    if (t < NBND) sb[t] = bnd[t];
    __syncthreads();

    int e = blockIdx.x * blockDim.x + t;
    if (e >= N_EDGES) return;

    int si = __ldg(&src[e]);
    int di = __ldg(&dst[e]);
    int p = atomicAdd(&g_cur[di], 1);

    float sx = __ldg(&loc[si * 3]), sy = __ldg(&loc[si * 3 + 1]), sz = __ldg(&loc[si * 3 + 2]);
    int others[5];
    others[0] = di;
#pragma unroll
    for (int k = 0; k < NUMK; k++) others[k + 1] = __ldg(&inter[(size_t)e * NUMK + k]);

    int pk[5];
#pragma unroll
    for (int s = 0; s < 5; s++) {
        int o = others[s];
        float bx = __ldg(&loc[o * 3]), by = __ldg(&loc[o * 3 + 1]), bz = __ldg(&loc[o * 3 + 2]);
        float dx = sx - bx, dy = sy - by, dz = sz - bz;
        float dv = sqrtf(dx * dx + dy * dy + dz * dz);
        int pos = 0;
#pragma unroll
        for (int step = 32; step >= 1; step >>= 1)
            if (pos + step <= NBND && sb[pos + step - 1] < dv) pos += step;
        pk[s] = (o << 6) | pos;
    }
    g_eh1[p] = make_int4(si, di, pk[0] & 63, pk[1]);
    g_eh2[p] = make_int4(pk[2], pk[3], pk[4], 0);
}

// One warp per 8 consecutive CSR slots; register-run accumulation,
// red.v4 flush only on dst change.
__global__ __launch_bounds__(256) void k_feat(const float* __restrict__ feat)
{
    int t = threadIdx.x;
    int lane = t & 31;
    int base = (blockIdx.x * 8 + (t >> 5)) * 8;
    if (base >= N_EDGES) return;

    int jpos = (lane < 16) ? lane * 4 : 64 + (lane - 16) * 4;
    int j2 = (lane < 16) ? lane * 4 : (lane - 16) * 4;

    float ax = 0.f, ay = 0.f, az = 0.f, aw = 0.f;
    float ssum = 0.f;
    int curdst = -1;

#pragma unroll
    for (int c = 0; c < 8; c++) {
        int4 h1 = __ldg(&g_eh1[base + c]);          // broadcast
        int si = h1.x, di = h1.y;
        if (di != curdst) {
            if (curdst >= 0) {
                red_add4(g_y + (size_t)curdst * 128 + jpos, ax, ay, az, aw);
                if (lane == 0) red_add1(&g_s[curdst], ssum);
            }
            ax = ay = az = aw = 0.f; ssum = 0.f;
            curdst = di;
        }
        float sc = rsqrtf(fmaxf((float)__ldg(&g_cin[di]), 1.f)) *
                   rsqrtf(fmaxf((float)__ldg(&g_cout[si]), 1.f));
        if (lane == 0) ssum += sc;
        if (lane < 16) {
            int b1 = h1.z;
            float4 h  = *reinterpret_cast<const float4*>(feat + (size_t)si * FDIM + j2);
            float4 tt = *reinterpret_cast<const float4*>(g_T + b1 * FDIM + j2);
            ax += sc * h.x * tt.x; ay += sc * h.y * tt.y;
            az += sc * h.z * tt.z; aw += sc * h.w * tt.w;
        } else {
            int4 h2 = __ldg(&g_eh2[base + c]);      // broadcast
            int pv[4] = {h1.w, h2.x, h2.y, h2.z};
            float tx = 0.f, ty = 0.f, tz = 0.f, tw = 0.f;
#pragma unroll
            for (int k = 0; k < NUMK; k++) {
                int id = pv[k] >> 6, bk = pv[k] & 63;
                float4 h  = *reinterpret_cast<const float4*>(feat + (size_t)id * FDIM + j2);
                float4 tt = *reinterpret_cast<const float4*>(g_T + bk * FDIM + j2);
                tx += h.x * tt.x; ty += h.y * tt.y;
                tz += h.z * tt.z; tw += h.w * tt.w;
            }
            float f4 = sc * 0.25f;
            ax += f4 * tx; ay += f4 * ty; az += f4 * tz; aw += f4 * tw;
        }
    }
    red_add4(g_y + (size_t)curdst * 128 + jpos, ax, ay, az, aw);
    if (lane == 0) red_add1(&g_s[curdst], ssum);
}

// out[v][f] = sum_j y[v][j] * W[f][j] + s[v] * b[f]
__global__ __launch_bounds__(256) void k_gemm(
    const float* __restrict__ W, const float* __restrict__ bvec,
    float* __restrict__ out)
{
    extern __shared__ float smem[];
    float* sW = smem;
    float* sY = smem + 128 * GP;
    int t = threadIdx.x;
    int vbase = blockIdx.x * 64;

    for (int idx = t; idx < FDIM * 128; idx += 256) {
        int f = idx >> 7, j = idx & 127;
        sW[j * GP + f] = W[idx];
    }
    for (int idx = t; idx < 64 * 128; idx += 256) {
        int v = idx >> 7, j = idx & 127;
        int gv = vbase + v;
        sY[j * GP + v] = (gv < N_NODES) ? g_y[(size_t)gv * 128 + j] : 0.f;
    }
    __syncthreads();

    int f0 = (t & 15) * 4;
    int v0 = (t >> 4) * 4;
    float acc[4][4];
#pragma unroll
    for (int a = 0; a < 4; a++)
#pragma unroll
        for (int b = 0; b < 4; b++) acc[a][b] = 0.f;

#pragma unroll 4
    for (int j = 0; j < 128; j++) {
        float4 wv = *reinterpret_cast<float4*>(&sW[j * GP + f0]);
        float4 yv = *reinterpret_cast<float4*>(&sY[j * GP + v0]);
        float wr[4] = {wv.x, wv.y, wv.z, wv.w};
        float yr[4] = {yv.x, yv.y, yv.z, yv.w};
#pragma unroll
        for (int a = 0; a < 4; a++)
#pragma unroll
            for (int b = 0; b < 4; b++) acc[a][b] += yr[a] * wr[b];
    }

    float4 bb = *reinterpret_cast<const float4*>(bvec + f0);
#pragma unroll
    for (int a = 0; a < 4; a++) {
        int v = vbase + v0 + a;
        if (v < N_NODES) {
            float sv = g_s[v];
            float4 o;
            o.x = acc[a][0] + sv * bb.x;
            o.y = acc[a][1] + sv * bb.y;
            o.z = acc[a][2] + sv * bb.z;
            o.w = acc[a][3] + sv * bb.w;
            *reinterpret_cast<float4*>(out + (size_t)v * FDIM + f0) = o;
        }
    }
}

extern "C" void kernel_launch(void* const* d_in, const int* in_sizes, int n_in,
                              void* d_out, int out_size) {
    const float* feat = (const float*)d_in[0];
    const float* loc  = (const float*)d_in[1];
    const float* bnd  = (const float*)d_in[2];
    const float* emb  = (const float*)d_in[3];
    const float* gw   = (const float*)d_in[4];
    const float* aggw = (const float*)d_in[5];
    const float* aggb = (const float*)d_in[6];
    const int* src   = (const int*)d_in[7];
    const int* dst   = (const int*)d_in[8];
    const int* inter = (const int*)d_in[9];
    float* out = (float*)d_out;

    k_prep<<<1024, 256>>>(emb, gw);                                   // 1
    k_hist<<<(N_EDGES + 255) / 256, 256>>>(src, dst);                 // 2
    k_scan<<<NSCAN, SCAN_B>>>();                                      // 3
    k_scat<<<(N_EDGES + 255) / 256, 256>>>(loc, bnd, src, dst, inter);// 4 (profiled)
    k_feat<<<(N_EDGES / 8 + 7) / 8, 256>>>(feat);                     // 5
    size_t smem = 2 * 128 * GP * sizeof(float);
    cudaFuncSetAttribute(k_gemm, cudaFuncAttributeMaxDynamicSharedMemorySize, (int)smem);
    k_gemm<<<(N_NODES + 63) / 64, 256, smem>>>(aggw, aggb, out);      // 6
}

// round 7
// speedup vs baseline: 1.1390x; 1.1390x over previous
#include <cuda_runtime.h>

#define N_NODES 50000
#define N_EDGES 500000
#define NUMK 4
#define FDIM 64
#define DDIM 32
#define NBE 64
#define NBND 63
#define GP 68

// Scratch (device globals)
__device__ __align__(128) float g_y[(size_t)N_NODES * 128];
__device__ float g_s[N_NODES];
__device__ int g_cin[N_NODES];
__device__ int g_cout[N_NODES];
__device__ __align__(128) float g_T[NBE * FDIM];
__device__ __align__(16) int4 g_ehA[N_EDGES];   // {si|di<<16, pk1, pk2, pk3}
__device__ __align__(16) int4 g_ehB[N_EDGES];   // {pk4, b1, sc_bits, 0}

__device__ __forceinline__ void red_add4(float* p, float x, float y, float z, float w) {
    asm volatile("red.global.add.v4.f32 [%0], {%1,%2,%3,%4};"
                 :: "l"(p), "f"(x), "f"(y), "f"(z), "f"(w));
}
__device__ __forceinline__ void red_add1(float* p, float x) {
    asm volatile("red.global.add.f32 [%0], %1;" :: "l"(p), "f"(x));
}

// Fused prep: zero y/s/counters, build T table.
__global__ __launch_bounds__(256) void k_prep(
    const float* __restrict__ emb, const float* __restrict__ gw)
{
    int i = blockIdx.x * blockDim.x + threadIdx.x;
    int stride = gridDim.x * blockDim.x;
    float4 z = make_float4(0.f, 0.f, 0.f, 0.f);
    float4* y4 = reinterpret_cast<float4*>(g_y);
    for (int j = i; j < N_NODES * 32; j += stride) y4[j] = z;
    for (int j = i; j < N_NODES; j += stride) {
        g_cin[j] = 0; g_cout[j] = 0; g_s[j] = 0.f;
    }
    for (int j = i; j < NBE * FDIM; j += stride) {
        int b = j >> 6, f = j & 63;
        float acc = 0.f;
#pragma unroll
        for (int d = 0; d < DDIM; d++) acc += emb[b * DDIM + d] * gw[f * DDIM + d];
        g_T[j] = acc;
    }
}

__global__ void k_deg(const int* __restrict__ src, const int* __restrict__ dst) {
    int e = blockIdx.x * blockDim.x + threadIdx.x;
    if (e < N_EDGES) {
        atomicAdd(&g_cin[dst[e]], 1);
        atomicAdd(&g_cout[src[e]], 1);
    }
}

// One thread per edge: all 5 distances + buckets + sc, packed header out
// (coalesced writes).
__global__ __launch_bounds__(256) void k_dist(
    const float* __restrict__ loc, const float* __restrict__ bnd,
    const int* __restrict__ src, const int* __restrict__ dst,
    const int* __restrict__ inter)
{
    __shared__ float sb[64];
    int t = threadIdx.x;
    if (t < NBND) sb[t] = bnd[t];
    __syncthreads();

    int e = blockIdx.x * blockDim.x + t;
    if (e >= N_EDGES) return;

    int si = __ldg(&src[e]);
    int di = __ldg(&dst[e]);
    float sx = __ldg(&loc[si * 3]), sy = __ldg(&loc[si * 3 + 1]), sz = __ldg(&loc[si * 3 + 2]);

    int others[5];
    others[0] = di;
#pragma unroll
    for (int k = 0; k < NUMK; k++) others[k + 1] = __ldg(&inter[(size_t)e * NUMK + k]);

    int pk[5];
#pragma unroll
    for (int s = 0; s < 5; s++) {
        int o = others[s];
        float bx = __ldg(&loc[o * 3]), by = __ldg(&loc[o * 3 + 1]), bz = __ldg(&loc[o * 3 + 2]);
        float dx = sx - bx, dy = sy - by, dz = sz - bz;
        float dv = sqrtf(dx * dx + dy * dy + dz * dz);
        int pos = 0;
#pragma unroll
        for (int step = 32; step >= 1; step >>= 1)
            if (pos + step <= NBND && sb[pos + step - 1] < dv) pos += step;
        pk[s] = (o << 6) | pos;
    }

    float sc = rsqrtf(fmaxf((float)__ldg(&g_cin[di]), 1.f)) *
               rsqrtf(fmaxf((float)__ldg(&g_cout[si]), 1.f));

    g_ehA[e] = make_int4(si | (di << 16), pk[1], pk[2], pk[3]);
    g_ehB[e] = make_int4(pk[4], pk[0] & 63, __float_as_int(sc), 0);
}

// Divergence-free: each warp handles 2 edges (lanes 0-15 -> edge A,
// 16-31 -> edge B). T table in shared memory. 5 independent passes.
__global__ __launch_bounds__(256) void k_feat(const float* __restrict__ feat)
{
    __shared__ __align__(16) float sT[NBE * FDIM];   // 16 KB
    int t = threadIdx.x;
    {
        float4* d4 = reinterpret_cast<float4*>(sT);
        const float4* s4 = reinterpret_cast<const float4*>(g_T);
#pragma unroll
        for (int k = 0; k < 4; k++) d4[t + 256 * k] = s4[t + 256 * k];
    }
    __syncthreads();

    int lane = t & 31;
    int hl = lane & 15;
    int half = lane >> 4;
    int e = (blockIdx.x * 8 + (t >> 5)) * 2 + half;   // 2 edges per warp
    if (e >= N_EDGES) return;

    int j = hl * 4;
    int4 A = __ldg(&g_ehA[e]);   // broadcast within half-warp
    int4 B = __ldg(&g_ehB[e]);
    int si = A.x & 0xffff;
    int di = (A.x >> 16) & 0xffff;
    float sc = __int_as_float(B.z);

    // pass 0: first half of cat = sc * T[b1] ⊙ h[src]
    float4 h0 = *reinterpret_cast<const float4*>(feat + (size_t)si * FDIM + j);
    float4 t0 = *reinterpret_cast<const float4*>(sT + B.y * FDIM + j);
    float r0x = sc * h0.x * t0.x, r0y = sc * h0.y * t0.y;
    float r0z = sc * h0.z * t0.z, r0w = sc * h0.w * t0.w;

    // passes 1-4: mean over sampled neighbors
    float ax = 0.f, ay = 0.f, az = 0.f, aw = 0.f;
    int pv[4] = {A.y, A.z, A.w, B.x};
#pragma unroll
    for (int k = 0; k < NUMK; k++) {
        int id = pv[k] >> 6, bk = pv[k] & 63;
        float4 h  = *reinterpret_cast<const float4*>(feat + (size_t)id * FDIM + j);
        float4 tv = *reinterpret_cast<const float4*>(sT + bk * FDIM + j);
        ax += h.x * tv.x; ay += h.y * tv.y;
        az += h.z * tv.z; aw += h.w * tv.w;
    }
    float f4 = sc * 0.25f;

    float* yrow = g_y + (size_t)di * 128;
    red_add4(yrow + j,      r0x, r0y, r0z, r0w);
    red_add4(yrow + 64 + j, f4 * ax, f4 * ay, f4 * az, f4 * aw);
    if (hl == 0) red_add1(&g_s[di], sc);
}

// out[v][f] = sum_j y[v][j] * W[f][j] + s[v] * b[f]
__global__ __launch_bounds__(256) void k_gemm(
    const float* __restrict__ W, const float* __restrict__ bvec,
    float* __restrict__ out)
{
    extern __shared__ float smem[];
    float* sW = smem;
    float* sY = smem + 128 * GP;
    int t = threadIdx.x;
    int vbase = blockIdx.x * 64;

    for (int idx = t; idx < FDIM * 128; idx += 256) {
        int f = idx >> 7, j = idx & 127;
        sW[j * GP + f] = W[idx];
    }
    for (int idx = t; idx < 64 * 128; idx += 256) {
        int v = idx >> 7, j = idx & 127;
        int gv = vbase + v;
        sY[j * GP + v] = (gv < N_NODES) ? g_y[(size_t)gv * 128 + j] : 0.f;
    }
    __syncthreads();

    int f0 = (t & 15) * 4;
    int v0 = (t >> 4) * 4;
    float acc[4][4];
#pragma unroll
    for (int a = 0; a < 4; a++)
#pragma unroll
        for (int b = 0; b < 4; b++) acc[a][b] = 0.f;

#pragma unroll 4
    for (int j = 0; j < 128; j++) {
        float4 wv = *reinterpret_cast<float4*>(&sW[j * GP + f0]);
        float4 yv = *reinterpret_cast<float4*>(&sY[j * GP + v0]);
        float wr[4] = {wv.x, wv.y, wv.z, wv.w};
        float yr[4] = {yv.x, yv.y, yv.z, yv.w};
#pragma unroll
        for (int a = 0; a < 4; a++)
#pragma unroll
            for (int b = 0; b < 4; b++) acc[a][b] += yr[a] * wr[b];
    }

    float4 bb = *reinterpret_cast<const float4*>(bvec + f0);
#pragma unroll
    for (int a = 0; a < 4; a++) {
        int v = vbase + v0 + a;
        if (v < N_NODES) {
            float sv = g_s[v];
            float4 o;
            o.x = acc[a][0] + sv * bb.x;
            o.y = acc[a][1] + sv * bb.y;
            o.z = acc[a][2] + sv * bb.z;
            o.w = acc[a][3] + sv * bb.w;
            *reinterpret_cast<float4*>(out + (size_t)v * FDIM + f0) = o;
        }
    }
}

extern "C" void kernel_launch(void* const* d_in, const int* in_sizes, int n_in,
                              void* d_out, int out_size) {
    const float* feat = (const float*)d_in[0];
    const float* loc  = (const float*)d_in[1];
    const float* bnd  = (const float*)d_in[2];
    const float* emb  = (const float*)d_in[3];
    const float* gw   = (const float*)d_in[4];
    const float* aggw = (const float*)d_in[5];
    const float* aggb = (const float*)d_in[6];
    const int* src   = (const int*)d_in[7];
    const int* dst   = (const int*)d_in[8];
    const int* inter = (const int*)d_in[9];
    float* out = (float*)d_out;

    k_prep<<<1024, 256>>>(emb, gw);                                    // 1
    k_deg<<<(N_EDGES + 255) / 256, 256>>>(src, dst);                   // 2
    k_dist<<<(N_EDGES + 255) / 256, 256>>>(loc, bnd, src, dst, inter); // 3
    k_feat<<<(N_EDGES / 2 + 7) / 8, 256>>>(feat);                      // 4 (profiled)
    size_t smem = 2 * 128 * GP * sizeof(float);
    cudaFuncSetAttribute(k_gemm, cudaFuncAttributeMaxDynamicSharedMemorySize, (int)smem);
    k_gemm<<<(N_NODES + 63) / 64, 256, smem>>>(aggw, aggb, out);       // 5
}

// round 8
// speedup vs baseline: 1.3366x; 1.1735x over previous
#include <cuda_runtime.h>
#include <cuda_fp16.h>

#define N_NODES 50000
#define N_EDGES 500000
#define NUMK 4
#define FDIM 64
#define DDIM 32
#define NBE 64
#define NBND 63
#define GP 68

// Scratch (device globals)
__device__ __align__(128) float g_y[(size_t)N_NODES * 128];
__device__ float g_s[N_NODES];
__device__ int g_cin[N_NODES];
__device__ int g_cout[N_NODES];
__device__ __align__(128) __half g_Th[NBE * FDIM];              // fp16 T table
__device__ __align__(128) __half g_fh[(size_t)N_NODES * FDIM];  // fp16 features
__device__ __align__(16) int4 g_ehA[N_EDGES];   // {si|di<<16, pk1, pk2, pk3}
__device__ __align__(16) int4 g_ehB[N_EDGES];   // {pk4, b1, sc_bits, 0}

__device__ __forceinline__ void red_add4(float* p, float x, float y, float z, float w) {
    asm volatile("red.global.add.v4.f32 [%0], {%1,%2,%3,%4};"
                 :: "l"(p), "f"(x), "f"(y), "f"(z), "f"(w));
}
__device__ __forceinline__ void red_add1(float* p, float x) {
    asm volatile("red.global.add.f32 [%0], %1;" :: "l"(p), "f"(x));
}

// Fused prep: zero y/s/counters, build fp16 T table, convert feat -> fp16.
__global__ __launch_bounds__(256) void k_prep(
    const float* __restrict__ emb, const float* __restrict__ gw,
    const float* __restrict__ feat)
{
    int i = blockIdx.x * blockDim.x + threadIdx.x;
    int stride = gridDim.x * blockDim.x;
    float4 z = make_float4(0.f, 0.f, 0.f, 0.f);
    float4* y4 = reinterpret_cast<float4*>(g_y);
    for (int j = i; j < N_NODES * 32; j += stride) y4[j] = z;
    for (int j = i; j < N_NODES; j += stride) {
        g_cin[j] = 0; g_cout[j] = 0; g_s[j] = 0.f;
    }
    // feat fp32 -> fp16
    const float2* f2 = reinterpret_cast<const float2*>(feat);
    __half2* h2 = reinterpret_cast<__half2*>(g_fh);
    for (int j = i; j < N_NODES * FDIM / 2; j += stride) {
        float2 v = f2[j];
        h2[j] = __floats2half2_rn(v.x, v.y);
    }
    // T[b][f] = sum_d emb[b][d]*gw[f][d], stored fp16
    for (int j = i; j < NBE * FDIM; j += stride) {
        int b = j >> 6, f = j & 63;
        float acc = 0.f;
#pragma unroll
        for (int d = 0; d < DDIM; d++) acc += emb[b * DDIM + d] * gw[f * DDIM + d];
        g_Th[j] = __float2half_rn(acc);
    }
}

__global__ void k_deg(const int* __restrict__ src, const int* __restrict__ dst) {
    int e = blockIdx.x * blockDim.x + threadIdx.x;
    if (e < N_EDGES) {
        atomicAdd(&g_cin[dst[e]], 1);
        atomicAdd(&g_cout[src[e]], 1);
    }
}

// One thread per edge: 5 distances + buckets + sc, packed header out.
__global__ __launch_bounds__(256) void k_dist(
    const float* __restrict__ loc, const float* __restrict__ bnd,
    const int* __restrict__ src, const int* __restrict__ dst,
    const int* __restrict__ inter)
{
    __shared__ float sb[64];
    int t = threadIdx.x;
    if (t < NBND) sb[t] = bnd[t];
    __syncthreads();

    int e = blockIdx.x * blockDim.x + t;
    if (e >= N_EDGES) return;

    int si = __ldg(&src[e]);
    int di = __ldg(&dst[e]);
    float sx = __ldg(&loc[si * 3]), sy = __ldg(&loc[si * 3 + 1]), sz = __ldg(&loc[si * 3 + 2]);

    int others[5];
    others[0] = di;
#pragma unroll
    for (int k = 0; k < NUMK; k++) others[k + 1] = __ldg(&inter[(size_t)e * NUMK + k]);

    int pk[5];
#pragma unroll
    for (int s = 0; s < 5; s++) {
        int o = others[s];
        float bx = __ldg(&loc[o * 3]), by = __ldg(&loc[o * 3 + 1]), bz = __ldg(&loc[o * 3 + 2]);
        float dx = sx - bx, dy = sy - by, dz = sz - bz;
        float dv = sqrtf(dx * dx + dy * dy + dz * dz);
        int pos = 0;
#pragma unroll
        for (int step = 32; step >= 1; step >>= 1)
            if (pos + step <= NBND && sb[pos + step - 1] < dv) pos += step;
        pk[s] = (o << 6) | pos;
    }

    float sc = rsqrtf(fmaxf((float)__ldg(&g_cin[di]), 1.f)) *
               rsqrtf(fmaxf((float)__ldg(&g_cout[si]), 1.f));

    g_ehA[e] = make_int4(si | (di << 16), pk[1], pk[2], pk[3]);
    g_ehB[e] = make_int4(pk[4], pk[0] & 63, __float_as_int(sc), 0);
}

// Divergence-free, fp16 data paths: 2 edges per warp (half-warp each),
// fp16 T in shared (8 KB), fp16 feat gathers (128 B/row), fp32 accumulation.
__global__ __launch_bounds__(256) void k_feat()
{
    __shared__ __align__(16) __half sT[NBE * FDIM];   // 8 KB
    int t = threadIdx.x;
    {
        uint2* d = reinterpret_cast<uint2*>(sT);
        const uint2* s = reinterpret_cast<const uint2*>(g_Th);
#pragma unroll
        for (int k = 0; k < 4; k++) d[t + 256 * k] = s[t + 256 * k];
    }
    __syncthreads();

    int lane = t & 31;
    int hl = lane & 15;
    int half = lane >> 4;
    int e = (blockIdx.x * 8 + (t >> 5)) * 2 + half;
    if (e >= N_EDGES) return;

    int j = hl * 4;
    int4 A = __ldg(&g_ehA[e]);
    int4 B = __ldg(&g_ehB[e]);
    int si = A.x & 0xffff;
    int di = (A.x >> 16) & 0xffff;
    float sc = __int_as_float(B.z);

    // pass 0: sc * T[b1] ⊙ h[src]
    uint2 hv = __ldg(reinterpret_cast<const uint2*>(g_fh + (size_t)si * FDIM + j));
    uint2 tv = *reinterpret_cast<const uint2*>(sT + B.y * FDIM + j);
    __half2 p0 = __hmul2(*reinterpret_cast<__half2*>(&hv.x), *reinterpret_cast<__half2*>(&tv.x));
    __half2 p1 = __hmul2(*reinterpret_cast<__half2*>(&hv.y), *reinterpret_cast<__half2*>(&tv.y));
    float2 f0 = __half22float2(p0), f1 = __half22float2(p1);
    float r0x = sc * f0.x, r0y = sc * f0.y, r0z = sc * f1.x, r0w = sc * f1.y;

    // passes 1-4: neighbor mean
    float ax = 0.f, ay = 0.f, az = 0.f, aw = 0.f;
    int pv[4] = {A.y, A.z, A.w, B.x};
#pragma unroll
    for (int k = 0; k < NUMK; k++) {
        int id = pv[k] >> 6, bk = pv[k] & 63;
        uint2 h = __ldg(reinterpret_cast<const uint2*>(g_fh + (size_t)id * FDIM + j));
        uint2 tt = *reinterpret_cast<const uint2*>(sT + bk * FDIM + j);
        __half2 q0 = __hmul2(*reinterpret_cast<__half2*>(&h.x), *reinterpret_cast<__half2*>(&tt.x));
        __half2 q1 = __hmul2(*reinterpret_cast<__half2*>(&h.y), *reinterpret_cast<__half2*>(&tt.y));
        float2 g0 = __half22float2(q0), g1 = __half22float2(q1);
        ax += g0.x; ay += g0.y; az += g1.x; aw += g1.y;
    }
    float f4 = sc * 0.25f;

    float* yrow = g_y + (size_t)di * 128;
    red_add4(yrow + j,      r0x, r0y, r0z, r0w);
    red_add4(yrow + 64 + j, f4 * ax, f4 * ay, f4 * az, f4 * aw);
    if (hl == 0) red_add1(&g_s[di], sc);
}

// out[v][f] = sum_j y[v][j] * W[f][j] + s[v] * b[f]
__global__ __launch_bounds__(256) void k_gemm(
    const float* __restrict__ W, const float* __restrict__ bvec,
    float* __restrict__ out)
{
    extern __shared__ float smem[];
    float* sW = smem;
    float* sY = smem + 128 * GP;
    int t = threadIdx.x;
    int vbase = blockIdx.x * 64;

    for (int idx = t; idx < FDIM * 128; idx += 256) {
        int f = idx >> 7, j = idx & 127;
        sW[j * GP + f] = W[idx];
    }
    for (int idx = t; idx < 64 * 128; idx += 256) {
        int v = idx >> 7, j = idx & 127;
        int gv = vbase + v;
        sY[j * GP + v] = (gv < N_NODES) ? g_y[(size_t)gv * 128 + j] : 0.f;
    }
    __syncthreads();

    int f0 = (t & 15) * 4;
    int v0 = (t >> 4) * 4;
    float acc[4][4];
#pragma unroll
    for (int a = 0; a < 4; a++)
#pragma unroll
        for (int b = 0; b < 4; b++) acc[a][b] = 0.f;

#pragma unroll 4
    for (int j = 0; j < 128; j++) {
        float4 wv = *reinterpret_cast<float4*>(&sW[j * GP + f0]);
        float4 yv = *reinterpret_cast<float4*>(&sY[j * GP + v0]);
        float wr[4] = {wv.x, wv.y, wv.z, wv.w};
        float yr[4] = {yv.x, yv.y, yv.z, yv.w};
#pragma unroll
        for (int a = 0; a < 4; a++)
#pragma unroll
            for (int b = 0; b < 4; b++) acc[a][b] += yr[a] * wr[b];
    }

    float4 bb = *reinterpret_cast<const float4*>(bvec + f0);
#pragma unroll
    for (int a = 0; a < 4; a++) {
        int v = vbase + v0 + a;
        if (v < N_NODES) {
            float sv = g_s[v];
            float4 o;
            o.x = acc[a][0] + sv * bb.x;
            o.y = acc[a][1] + sv * bb.y;
            o.z = acc[a][2] + sv * bb.z;
            o.w = acc[a][3] + sv * bb.w;
            *reinterpret_cast<float4*>(out + (size_t)v * FDIM + f0) = o;
        }
    }
}

extern "C" void kernel_launch(void* const* d_in, const int* in_sizes, int n_in,
                              void* d_out, int out_size) {
    const float* feat = (const float*)d_in[0];
    const float* loc  = (const float*)d_in[1];
    const float* bnd  = (const float*)d_in[2];
    const float* emb  = (const float*)d_in[3];
    const float* gw   = (const float*)d_in[4];
    const float* aggw = (const float*)d_in[5];
    const float* aggb = (const float*)d_in[6];
    const int* src   = (const int*)d_in[7];
    const int* dst   = (const int*)d_in[8];
    const int* inter = (const int*)d_in[9];
    float* out = (float*)d_out;

    k_prep<<<1024, 256>>>(emb, gw, feat);                              // 1
    k_deg<<<(N_EDGES + 255) / 256, 256>>>(src, dst);                   // 2
    k_dist<<<(N_EDGES + 255) / 256, 256>>>(loc, bnd, src, dst, inter); // 3
    k_feat<<<(N_EDGES / 2 + 7) / 8, 256>>>();                          // 4 (profiled)
    size_t smem = 2 * 128 * GP * sizeof(float);
    cudaFuncSetAttribute(k_gemm, cudaFuncAttributeMaxDynamicSharedMemorySize, (int)smem);
    k_gemm<<<(N_NODES + 63) / 64, 256, smem>>>(aggw, aggb, out);       // 5
}

// round 10
// speedup vs baseline: 1.4158x; 1.0592x over previous
#include <cuda_runtime.h>
#include <cuda_fp16.h>

#define N_NODES 50000
#define N_EDGES 500000
#define NUMK 4
#define FDIM 64
#define DDIM 32
#define NBE 64
#define NBND 63
#define GP 68

// Scratch (device globals)
__device__ __align__(128) float g_y[(size_t)N_NODES * 128];
__device__ float g_s[N_NODES];
__device__ int g_cin[N_NODES];
__device__ int g_cout[N_NODES];
__device__ __align__(128) __half g_Th[NBE * FDIM];              // fp16 T table
__device__ __align__(128) __half g_fh[(size_t)N_NODES * FDIM];  // fp16 features
__device__ __align__(16) float4 g_loc4[N_NODES];                // padded positions
__device__ __align__(16) int4 g_ehA[N_EDGES];   // {si|di<<16, pk1, pk2, pk3}
__device__ __align__(16) int4 g_ehB[N_EDGES];   // {pk4, b1, sc_bits, 0}

__device__ __forceinline__ void red_add4(float* p, float x, float y, float z, float w) {
    asm volatile("red.global.add.v4.f32 [%0], {%1,%2,%3,%4};"
                 :: "l"(p), "f"(x), "f"(y), "f"(z), "f"(w));
}
__device__ __forceinline__ void red_add1(float* p, float x) {
    asm volatile("red.global.add.f32 [%0], %1;" :: "l"(p), "f"(x));
}
// packed f32x2 fma: d = a*b + d   (a,b,d are b64 register pairs)
__device__ __forceinline__ void ffma2(unsigned long long& d,
                                      unsigned long long a, unsigned long long b) {
    asm("fma.rn.f32x2 %0, %1, %2, %0;" : "+l"(d) : "l"(a), "l"(b));
}
__device__ __forceinline__ unsigned long long pack2(float lo, float hi) {
    unsigned long long r;
    asm("mov.b64 %0, {%1, %2};" : "=l"(r) : "f"(lo), "f"(hi));
    return r;
}

// Fused prep: zero y/s/counters, fp16 T table, fp16 feat, padded loc4.
__global__ __launch_bounds__(256) void k_prep(
    const float* __restrict__ emb, const float* __restrict__ gw,
    const float* __restrict__ feat, const float* __restrict__ loc)
{
    int i = blockIdx.x * blockDim.x + threadIdx.x;
    int stride = gridDim.x * blockDim.x;
    float4 z = make_float4(0.f, 0.f, 0.f, 0.f);
    float4* y4 = reinterpret_cast<float4*>(g_y);
    for (int j = i; j < N_NODES * 32; j += stride) y4[j] = z;
    for (int j = i; j < N_NODES; j += stride) {
        g_cin[j] = 0; g_cout[j] = 0; g_s[j] = 0.f;
        g_loc4[j] = make_float4(loc[j * 3], loc[j * 3 + 1], loc[j * 3 + 2], 0.f);
    }
    const float2* f2 = reinterpret_cast<const float2*>(feat);
    __half2* h2 = reinterpret_cast<__half2*>(g_fh);
    for (int j = i; j < N_NODES * FDIM / 2; j += stride) {
        float2 v = f2[j];
        h2[j] = __floats2half2_rn(v.x, v.y);
    }
    for (int j = i; j < NBE * FDIM; j += stride) {
        int b = j >> 6, f = j & 63;
        float acc = 0.f;
#pragma unroll
        for (int d = 0; d < DDIM; d++) acc += emb[b * DDIM + d] * gw[f * DDIM + d];
        g_Th[j] = __float2half_rn(acc);
    }
}

__global__ void k_deg(const int* __restrict__ src, const int* __restrict__ dst) {
    int e = blockIdx.x * blockDim.x + threadIdx.x;
    if (e < N_EDGES) {
        atomicAdd(&g_cin[dst[e]], 1);
        atomicAdd(&g_cout[src[e]], 1);
    }
}

// One thread per edge: 5 distances + buckets + sc (also REDs g_s here).
__global__ __launch_bounds__(256) void k_dist(
    const float* __restrict__ bnd,
    const int* __restrict__ src, const int* __restrict__ dst,
    const int* __restrict__ inter)
{
    __shared__ float sb[64];
    int t = threadIdx.x;
    if (t < NBND) sb[t] = bnd[t];
    __syncthreads();

    int e = blockIdx.x * blockDim.x + t;
    if (e >= N_EDGES) return;

    int si = __ldg(&src[e]);
    int di = __ldg(&dst[e]);
    float4 sp = __ldg(&g_loc4[si]);

    int others[5];
    others[0] = di;
#pragma unroll
    for (int k = 0; k < NUMK; k++) others[k + 1] = __ldg(&inter[(size_t)e * NUMK + k]);

    int pk[5];
#pragma unroll
    for (int s = 0; s < 5; s++) {
        int o = others[s];
        float4 op = __ldg(&g_loc4[o]);
        float dx = sp.x - op.x, dy = sp.y - op.y, dz = sp.z - op.z;
        float dv = sqrtf(dx * dx + dy * dy + dz * dz);
        int pos = 0;
#pragma unroll
        for (int step = 32; step >= 1; step >>= 1)
            if (pos + step <= NBND && sb[pos + step - 1] < dv) pos += step;
        pk[s] = (o << 6) | pos;
    }

    float sc = rsqrtf(fmaxf((float)__ldg(&g_cin[di]), 1.f)) *
               rsqrtf(fmaxf((float)__ldg(&g_cout[si]), 1.f));
    red_add1(&g_s[di], sc);

    g_ehA[e] = make_int4(si | (di << 16), pk[1], pk[2], pk[3]);
    g_ehB[e] = make_int4(pk[4], pk[0] & 63, __float_as_int(sc), 0);
}

// Divergence-free fp16 k_feat: 2 edges per warp, fp16 T in shared.
__global__ __launch_bounds__(256) void k_feat()
{
    __shared__ __align__(16) __half sT[NBE * FDIM];   // 8 KB
    int t = threadIdx.x;
    {
        uint2* d = reinterpret_cast<uint2*>(sT);
        const uint2* s = reinterpret_cast<const uint2*>(g_Th);
#pragma unroll
        for (int k = 0; k < 4; k++) d[t + 256 * k] = s[t + 256 * k];
    }
    __syncthreads();

    int lane = t & 31;
    int hl = lane & 15;
    int half = lane >> 4;
    int e = (blockIdx.x * 8 + (t >> 5)) * 2 + half;
    if (e >= N_EDGES) return;

    int j = hl * 4;
    int4 A = __ldg(&g_ehA[e]);
    int4 B = __ldg(&g_ehB[e]);
    int si = A.x & 0xffff;
    int di = (A.x >> 16) & 0xffff;
    float sc = __int_as_float(B.z);

    uint2 hv = __ldg(reinterpret_cast<const uint2*>(g_fh + (size_t)si * FDIM + j));
    uint2 tv = *reinterpret_cast<const uint2*>(sT + B.y * FDIM + j);
    __half2 p0 = __hmul2(*reinterpret_cast<__half2*>(&hv.x), *reinterpret_cast<__half2*>(&tv.x));
    __half2 p1 = __hmul2(*reinterpret_cast<__half2*>(&hv.y), *reinterpret_cast<__half2*>(&tv.y));
    float2 f0 = __half22float2(p0), f1 = __half22float2(p1);
    float r0x = sc * f0.x, r0y = sc * f0.y, r0z = sc * f1.x, r0w = sc * f1.y;

    float ax = 0.f, ay = 0.f, az = 0.f, aw = 0.f;
    int pv[4] = {A.y, A.z, A.w, B.x};
#pragma unroll
    for (int k = 0; k < NUMK; k++) {
        int id = pv[k] >> 6, bk = pv[k] & 63;
        uint2 h = __ldg(reinterpret_cast<const uint2*>(g_fh + (size_t)id * FDIM + j));
        uint2 tt = *reinterpret_cast<const uint2*>(sT + bk * FDIM + j);
        __half2 q0 = __hmul2(*reinterpret_cast<__half2*>(&h.x), *reinterpret_cast<__half2*>(&tt.x));
        __half2 q1 = __hmul2(*reinterpret_cast<__half2*>(&h.y), *reinterpret_cast<__half2*>(&tt.y));
        float2 g0 = __half22float2(q0), g1 = __half22float2(q1);
        ax += g0.x; ay += g0.y; az += g1.x; aw += g1.y;
    }
    float f4 = sc * 0.25f;

    float* yrow = g_y + (size_t)di * 128;
    red_add4(yrow + j,      r0x, r0y, r0z, r0w);
    red_add4(yrow + 64 + j, f4 * ax, f4 * ay, f4 * az, f4 * aw);
}

// out[v][f] = sum_j y[v][j] * W[f][j] + s[v] * b[f]
// Inner product via packed fma.rn.f32x2 (2 MACs/instr, full fp32).
__global__ __launch_bounds__(256) void k_gemm(
    const float* __restrict__ W, const float* __restrict__ bvec,
    float* __restrict__ out)
{
    extern __shared__ float smem[];
    float* sW = smem;
    float* sY = smem + 128 * GP;
    int t = threadIdx.x;
    int vbase = blockIdx.x * 64;

    for (int idx = t; idx < FDIM * 128; idx += 256) {
        int f = idx >> 7, j = idx & 127;
        sW[j * GP + f] = W[idx];
    }
    for (int idx = t; idx < 64 * 128; idx += 256) {
        int v = idx >> 7, j = idx & 127;
        int gv = vbase + v;
        sY[j * GP + v] = (gv < N_NODES) ? g_y[(size_t)gv * 128 + j] : 0.f;
    }
    __syncthreads();

    int f0 = (t & 15) * 4;
    int v0 = (t >> 4) * 4;
    // acc packed over f: accp[a][pb], pb=0 -> (f0,f0+1), pb=1 -> (f0+2,f0+3)
    unsigned long long accp[4][2];
#pragma unroll
    for (int a = 0; a < 4; a++) { accp[a][0] = 0ull; accp[a][1] = 0ull; }

#pragma unroll 4
    for (int j = 0; j < 128; j++) {
        float4 wv = *reinterpret_cast<float4*>(&sW[j * GP + f0]);
        float4 yv = *reinterpret_cast<float4*>(&sY[j * GP + v0]);
        unsigned long long wp0 = pack2(wv.x, wv.y);
        unsigned long long wp1 = pack2(wv.z, wv.w);
        float yr[4] = {yv.x, yv.y, yv.z, yv.w};
#pragma unroll
        for (int a = 0; a < 4; a++) {
            unsigned long long yb = pack2(yr[a], yr[a]);
            ffma2(accp[a][0], yb, wp0);
            ffma2(accp[a][1], yb, wp1);
        }
    }

    float4 bb = *reinterpret_cast<const float4*>(bvec + f0);
#pragma unroll
    for (int a = 0; a < 4; a++) {
        int v = vbase + v0 + a;
        if (v < N_NODES) {
            float sv = g_s[v];
            float2 c0 = *reinterpret_cast<float2*>(&accp[a][0]);
            float2 c1 = *reinterpret_cast<float2*>(&accp[a][1]);
            float4 o;
            o.x = c0.x + sv * bb.x;
            o.y = c0.y + sv * bb.y;
            o.z = c1.x + sv * bb.z;
            o.w = c1.y + sv * bb.w;
            *reinterpret_cast<float4*>(out + (size_t)v * FDIM + f0) = o;
        }
    }
}

extern "C" void kernel_launch(void* const* d_in, const int* in_sizes, int n_in,
                              void* d_out, int out_size) {
    const float* feat = (const float*)d_in[0];
    const float* loc  = (const float*)d_in[1];
    const float* bnd  = (const float*)d_in[2];
    const float* emb  = (const float*)d_in[3];
    const float* gw   = (const float*)d_in[4];
    const float* aggw = (const float*)d_in[5];
    const float* aggb = (const float*)d_in[6];
    const int* src   = (const int*)d_in[7];
    const int* dst   = (const int*)d_in[8];
    const int* inter = (const int*)d_in[9];
    float* out = (float*)d_out;

    k_prep<<<1024, 256>>>(emb, gw, feat, loc);                     // 1
    k_deg<<<(N_EDGES + 255) / 256, 256>>>(src, dst);               // 2
    k_dist<<<(N_EDGES + 255) / 256, 256>>>(bnd, src, dst, inter);  // 3
    k_feat<<<(N_EDGES / 2 + 7) / 8, 256>>>();                      // 4 (profiled)
    size_t smem = 2 * 128 * GP * sizeof(float);
    cudaFuncSetAttribute(k_gemm, cudaFuncAttributeMaxDynamicSharedMemorySize, (int)smem);
    k_gemm<<<(N_NODES + 63) / 64, 256, smem>>>(aggw, aggb, out);   // 5
}